// round 17
// baseline (speedup 1.0000x reference)
#include <cuda_runtime.h>
#include <cuda_fp16.h>
#include <cstdint>

#define H    8
#define Bn   32768
#define OF   32
#define NKS  36            // ksteps of 16 -> K = 576
#define MT   128           // samples per CTA (2 warp-pairs x 64)
#define NT   128           // 4 warps; pair = wid>>1, n-half = wid&1

// W fragments (single fp16 plane), packed for LDG.128:
// uint4 idx = ((h*NKS+ks)*2+ntp)*32+lane   (ntp = n-half)
__device__ uint4 g_wf4[H * NKS * 2 * 32];

// smem per warp-pair: cph[ch*33+sp] packed half2 (1056 u32) + xsw[i*65+s] fp32 (1040 f)
// cph entry at sp = m*8+gg  holds (cond[s], cond[s+8]) with s = gg + 16m
#define PBLK  2096                     // u32 words per pair
#define SM_TOTAL (2 * PBLK * 4)        // 16768 bytes

static __device__ __forceinline__ uint32_t cvt2(float p0, float p1) {
    __half2 hv = __floats2half2_rn(p0, p1);
    return *reinterpret_cast<uint32_t*>(&hv);
}
static __device__ __forceinline__ uint32_t hmul2u(uint32_t a, uint32_t b) {
    __half2 r = __hmul2(*reinterpret_cast<__half2*>(&a), *reinterpret_cast<__half2*>(&b));
    return *reinterpret_cast<uint32_t*>(&r);
}
static __device__ __forceinline__ uint32_t low2u(uint32_t a) {
    __half2 r = __low2half2(*reinterpret_cast<__half2*>(&a));
    return *reinterpret_cast<uint32_t*>(&r);
}
static __device__ __forceinline__ uint32_t high2u(uint32_t a) {
    __half2 r = __high2half2(*reinterpret_cast<__half2*>(&a));
    return *reinterpret_cast<uint32_t*>(&r);
}
static __device__ __forceinline__ uint32_t lows2(uint32_t a, uint32_t b) {
    __half2 r = __lows2half2(*reinterpret_cast<__half2*>(&a), *reinterpret_cast<__half2*>(&b));
    return *reinterpret_cast<uint32_t*>(&r);
}
static __device__ __forceinline__ uint32_t highs2(uint32_t a, uint32_t b) {
    __half2 r = __highs2half2(*reinterpret_cast<__half2*>(&a), *reinterpret_cast<__half2*>(&b));
    return *reinterpret_cast<uint32_t*>(&r);
}
static __device__ __forceinline__ void mma_f16(float d[4], const uint32_t a[4],
                                               uint32_t b0, uint32_t b1) {
    asm volatile(
        "mma.sync.aligned.m16n8k16.row.col.f32.f16.f16.f32 "
        "{%0,%1,%2,%3}, {%4,%5,%6,%7}, {%8,%9}, {%0,%1,%2,%3};"
        : "+f"(d[0]), "+f"(d[1]), "+f"(d[2]), "+f"(d[3])
        : "r"(a[0]), "r"(a[1]), "r"(a[2]), "r"(a[3]), "r"(b0), "r"(b1));
}

// permuted W': kp<512: W[o*17+(kp&15)][ch=kp>>4]; 512+i: bias(i); 528+q: W[o*17+16][q];
//              560: bias(16); else 0
static __device__ __forceinline__ float wval(const float* cw, const float* cb,
                                             int h, int kp, int o) {
    if (kp < 512) { int ch = kp >> 4, i = kp & 15; return cw[(h * 544 + o * 17 + i) * 32 + ch]; }
    if (kp < 528) return cb[h * 544 + o * 17 + (kp - 512)];
    if (kp < 560) return cw[(h * 544 + o * 17 + 16) * 32 + (kp - 528)];
    if (kp == 560) return cb[h * 544 + o * 17 + 16];
    return 0.0f;
}
__global__ void mml_prep_k(const float* __restrict__ cw, const float* __restrict__ cb) {
    int idx = blockIdx.x * blockDim.x + threadIdx.x;
    if (idx >= H * NKS * 2 * 32) return;
    int lane = idx & 31;
    int ntp  = (idx >> 5) & 1;
    int ks   = (idx >> 6) % NKS;
    int h    = (idx >> 6) / NKS;
    int g = lane >> 2, t = lane & 3;
    uint32_t v[4];
#pragma unroll
    for (int p = 0; p < 2; p++) {
        int o = (ntp * 2 + p) * 8 + g;
#pragma unroll
        for (int j = 0; j < 2; j++) {
            int k0 = ks * 16 + 2 * t + 8 * j;
            v[p * 2 + j] = cvt2(wval(cw, cb, h, k0, o), wval(cw, cb, h, k0 + 1, o));
        }
    }
    g_wf4[idx] = make_uint4(v[0], v[1], v[2], v[3]);
}

__global__ void __launch_bounds__(NT, 5)
mml_k(const float* __restrict__ input, const float* __restrict__ cond,
      float* __restrict__ out) {
    extern __shared__ uint32_t smu[];
    const int tid = threadIdx.x;
    const int wid = tid >> 5;
    const int lane = tid & 31;
    const int pair = wid >> 1;       // 0,1 : which 64-sample group
    const int ntp = wid & 1;         // which 16-wide N half
    const int h = blockIdx.y;
    const size_t sbase = (size_t)(h * Bn + blockIdx.x * MT);
    const size_t prow = sbase + pair * 64;     // pair's first sample

    uint32_t* cph = smu + pair * PBLK;                   // packed (c_s, c_s+8)
    float* xsw = reinterpret_cast<float*>(cph + 1056);   // fp32 x: [i*65 + s]

    // ---- pair staging: each warp of the pair stages complementary halves ----
    {
        const int pw = wid & 1;
        const float* cg = cond + prow * 32;
#pragma unroll
        for (int j = 0; j < 16; j++) {
            int sp = pw * 16 + j;
            int m = sp >> 3;
            int s = (sp & 7) + 16 * m;       // pw=0: s in 0..7,16..23 ; pw=1: 32..39,48..55
            cph[lane * 33 + sp] = cvt2(cg[s * 32 + lane], cg[(s + 8) * 32 + lane]);
        }
        int s = pw * 32 + lane;
        const float4* xg = reinterpret_cast<const float4*>(input + (prow + s) * 16);
#pragma unroll
        for (int q = 0; q < 4; q++) {
            float4 v = xg[q];
            xsw[(q * 4 + 0) * 65 + s] = v.x;
            xsw[(q * 4 + 1) * 65 + s] = v.y;
            xsw[(q * 4 + 2) * 65 + s] = v.z;
            xsw[(q * 4 + 3) * 65 + s] = v.w;
        }
    }
    __syncthreads();

    // per-lane x as half2 pairs, A-fragment layout; 8 rows: r*8+g (r = 2*tt + half)
    const int g = lane >> 2, t = lane & 3;
    uint32_t xh[8][2];
#pragma unroll
    for (int r = 0; r < 8; r++) {
        int s = r * 8 + g;
        xh[r][0] = cvt2(xsw[(2 * t) * 65 + s],     xsw[(2 * t + 1) * 65 + s]);
        xh[r][1] = cvt2(xsw[(2 * t + 8) * 65 + s], xsw[(2 * t + 9) * 65 + s]);
    }

    float d[8][4];
#pragma unroll
    for (int n = 0; n < 8; n++)
#pragma unroll
        for (int e = 0; e < 4; e++) d[n][e] = 0.0f;

    // W stream: this warp's n-half only -> 1 LDG.128 per kstep
    const uint4* wp = g_wf4 + ((size_t)(h * NKS) * 2 + ntp) * 32 + lane;

    auto do_mmas = [&](const uint32_t a[4][4], uint4 w) {
#pragma unroll
        for (int tt = 0; tt < 4; tt++) {
            mma_f16(d[tt * 2 + 0], a[tt], w.x, w.y);
            mma_f16(d[tt * 2 + 1], a[tt], w.z, w.w);
        }
    };

    uint4 wA = wp[0];

    // ---- ksteps 0..31: P = cond[ks] * x[i] ----
#pragma unroll 1
    for (int c = 0; c < 8; c++) {
#pragma unroll
        for (int u = 0; u < 4; u++) {
            const int ks = c * 4 + u;
            uint4 nwA = wp[(ks + 1) * 64];
            const uint32_t* cn = cph + ks * 33;
            uint32_t p0 = cn[g];            // (c[r0], c[r0+8]) for tt=0
            uint32_t p1 = cn[8 + g];
            uint32_t p2 = cn[16 + g];
            uint32_t p3 = cn[24 + g];
            uint32_t a[4][4];
            uint32_t cl, ch_;
            cl = low2u(p0); ch_ = high2u(p0);
            a[0][0] = hmul2u(cl, xh[0][0]); a[0][1] = hmul2u(ch_, xh[1][0]);
            a[0][2] = hmul2u(cl, xh[0][1]); a[0][3] = hmul2u(ch_, xh[1][1]);
            cl = low2u(p1); ch_ = high2u(p1);
            a[1][0] = hmul2u(cl, xh[2][0]); a[1][1] = hmul2u(ch_, xh[3][0]);
            a[1][2] = hmul2u(cl, xh[2][1]); a[1][3] = hmul2u(ch_, xh[3][1]);
            cl = low2u(p2); ch_ = high2u(p2);
            a[2][0] = hmul2u(cl, xh[4][0]); a[2][1] = hmul2u(ch_, xh[5][0]);
            a[2][2] = hmul2u(cl, xh[4][1]); a[2][3] = hmul2u(ch_, xh[5][1]);
            cl = low2u(p3); ch_ = high2u(p3);
            a[3][0] = hmul2u(cl, xh[6][0]); a[3][1] = hmul2u(ch_, xh[7][0]);
            a[3][2] = hmul2u(cl, xh[6][1]); a[3][3] = hmul2u(ch_, xh[7][1]);
            do_mmas(a, wA);
            wA = nwA;
        }
    }
    // ---- kstep 32: P = x[i] (cv = 1); W already prefetched in wA ----
    {
        uint32_t a[4][4];
#pragma unroll
        for (int tt = 0; tt < 4; tt++) {
            a[tt][0] = xh[tt * 2 + 0][0];
            a[tt][1] = xh[tt * 2 + 1][0];
            a[tt][2] = xh[tt * 2 + 0][1];
            a[tt][3] = xh[tt * 2 + 1][1];
        }
        do_mmas(a, wA);
    }
    // ---- ksteps 33,34: P = cond[qb + kcol] ----
#pragma unroll
    for (int u = 0; u < 2; u++) {
        const int ks = 33 + u;
        const int qb = u * 16;
        const int i0 = 2 * t, i1 = 2 * t + 1, i2 = 2 * t + 8, i3 = 2 * t + 9;
        uint4 w = wp[ks * 64];
        uint32_t a[4][4];
#pragma unroll
        for (int tt = 0; tt < 4; tt++) {
            int sp = tt * 8 + g;             // entry holds (c[r0], c[r0+8]), r0 = tt*16+g
            uint32_t e0 = cph[(qb + i0) * 33 + sp];
            uint32_t e1 = cph[(qb + i1) * 33 + sp];
            uint32_t e2 = cph[(qb + i2) * 33 + sp];
            uint32_t e3 = cph[(qb + i3) * 33 + sp];
            a[tt][0] = lows2(e0, e1);
            a[tt][1] = highs2(e0, e1);
            a[tt][2] = lows2(e2, e3);
            a[tt][3] = highs2(e2, e3);
        }
        do_mmas(a, w);
    }
    // ---- kstep 35: P[.,560] = 1.0, rest 0 ----
    {
        uint4 w = wp[35 * 64];
        uint32_t one = (t == 0) ? 0x00003C00u : 0u;
        uint32_t a[4][4];
#pragma unroll
        for (int tt = 0; tt < 4; tt++) {
            a[tt][0] = one; a[tt][1] = one; a[tt][2] = 0u; a[tt][3] = 0u;
        }
        do_mmas(a, w);
    }

    // ---- epilogue: rows prow + tt*16 + {g, g+8}, cols ntp*16 + nt*8 + 2*t4 ----
    {
        const int t4 = lane & 3;
#pragma unroll
        for (int tt = 0; tt < 4; tt++) {
#pragma unroll
            for (int nt = 0; nt < 2; nt++) {
                const float* dd = d[tt * 2 + nt];
                int col = ntp * 16 + nt * 8 + 2 * t4;
                size_t r0 = prow + tt * 16 + g;
                *reinterpret_cast<float2*>(out + r0 * OF + col) = make_float2(dd[0], dd[1]);
                *reinterpret_cast<float2*>(out + (r0 + 8) * OF + col) = make_float2(dd[2], dd[3]);
            }
        }
    }
}

extern "C" void kernel_launch(void* const* d_in, const int* in_sizes, int n_in,
                              void* d_out, int out_size) {
    const float* input = (const float*)d_in[0];
    const float* cond  = (const float*)d_in[1];
    const float* cw    = (const float*)d_in[2];
    const float* cb    = (const float*)d_in[3];
    float* out = (float*)d_out;

    int prep = H * NKS * 2 * 32;   // 18432
    mml_prep_k<<<(prep + 255) / 256, 256>>>(cw, cb);

    cudaFuncSetAttribute(mml_k, cudaFuncAttributeMaxDynamicSharedMemorySize, SM_TOTAL);
    dim3 grid(Bn / MT, H);         // (256, 8)
    mml_k<<<grid, NT, SM_TOTAL>>>(input, cond, out);
}